// round 9
// baseline (speedup 1.0000x reference)
#include <cuda_runtime.h>
#include <cuda_fp16.h>
#include <cstdint>

// Problem constants
#define TOKENS   4096
#define IN_F     4096
#define OUT_F    11008
#define QGROUPS  64
#define KWORDS   (IN_F / 8)       // 512 packed int32 per output row

// GEMM tiling: 64x128 tiles, 3 CTAs/SM, persistent grid, cross-tile pipeline.
#define BM       64
#define BN       128
#define BK       64               // fp16 elements per stage along K (128B rows)
#define NSTAGE   3
#define NKIT     (IN_F / BK)      // 64
#define NTHREADS 128              // 4 warps, 2x2 grid of 32x64 warp tiles
#define A_STAGE_BYTES (BM * BK * 2)               // 8192
#define B_STAGE_BYTES (BN * BK * 2)               // 16384
#define STAGE_BYTES   (A_STAGE_BYTES + B_STAGE_BYTES)  // 24576
#define SMEM_TOTAL    (NSTAGE * STAGE_BYTES)      // 73728 (3 CTAs -> 216KB/SM)

#define NMT      (TOKENS / BM)    // 64 M tiles
#define NNT      (OUT_F / BN)     // 86 N tiles
#define NTILES   (NMT * NNT)      // 5504
#define NCTAS    444              // 148 SMs * 3 CTAs

// Scratch (device globals: allocation-free rule)
__device__ __half g_Bh[(size_t)OUT_F * IN_F];   // dequantized fp16 weights
__device__ __half g_Xh[(size_t)TOKENS * IN_F];  // fp16 activations

// ---------------------------------------------------------------------------
// Helpers
// ---------------------------------------------------------------------------
__device__ __forceinline__ uint32_t smem_u32(const void* p) {
    uint32_t a;
    asm("{ .reg .u64 t; cvta.to.shared.u64 t, %1; cvt.u32.u64 %0, t; }"
        : "=r"(a) : "l"(p));
    return a;
}

__device__ __forceinline__ void ldsm_x4(uint32_t addr, uint32_t* r) {
    asm volatile("ldmatrix.sync.aligned.m8n8.x4.shared.b16 {%0,%1,%2,%3}, [%4];"
                 : "=r"(r[0]), "=r"(r[1]), "=r"(r[2]), "=r"(r[3]) : "r"(addr));
}

__device__ __forceinline__ void mma16816(float* c, const uint32_t* a,
                                         uint32_t b0, uint32_t b1) {
    asm volatile(
        "mma.sync.aligned.m16n8k16.row.col.f32.f16.f16.f32 "
        "{%0,%1,%2,%3}, {%4,%5,%6,%7}, {%8,%9}, {%0,%1,%2,%3};"
        : "+f"(c[0]), "+f"(c[1]), "+f"(c[2]), "+f"(c[3])
        : "r"(a[0]), "r"(a[1]), "r"(a[2]), "r"(a[3]), "r"(b0), "r"(b1));
}

// ---------------------------------------------------------------------------
// Fused pre-kernel: blocks [0, NCONV) convert x -> fp16; the rest dequantize
// int4 weights -> fp16. The two jobs are independent and run concurrently.
// ---------------------------------------------------------------------------
#define NCONV_ELEMS (TOKENS * IN_F / 8)           // uint4 stores: 2097152
#define NCONV_BLKS  ((NCONV_ELEMS + 255) / 256)   // 8192
#define NDEQ_ELEMS  (OUT_F * KWORDS)              // 5636096
#define NDEQ_BLKS   ((NDEQ_ELEMS + 255) / 256)    // 22016

__global__ void prep_kernel(const float4* __restrict__ x,
                            const uint32_t* __restrict__ qw,
                            const uint32_t* __restrict__ qz,
                            const float* __restrict__ sc) {
    if (blockIdx.x < NCONV_BLKS) {
        int i = blockIdx.x * 256 + threadIdx.x;
        if (i >= NCONV_ELEMS) return;
        float4 a = x[2 * i];
        float4 b = x[2 * i + 1];
        __half2 h0 = __floats2half2_rn(a.x, a.y);
        __half2 h1 = __floats2half2_rn(a.z, a.w);
        __half2 h2 = __floats2half2_rn(b.x, b.y);
        __half2 h3 = __floats2half2_rn(b.z, b.w);
        uint4 o;
        o.x = *reinterpret_cast<uint32_t*>(&h0);
        o.y = *reinterpret_cast<uint32_t*>(&h1);
        o.z = *reinterpret_cast<uint32_t*>(&h2);
        o.w = *reinterpret_cast<uint32_t*>(&h3);
        reinterpret_cast<uint4*>(g_Xh)[i] = o;
    } else {
        int idx = (blockIdx.x - NCONV_BLKS) * 256 + threadIdx.x;
        if (idx >= NDEQ_ELEMS) return;
        int o  = idx >> 9;              // / 512
        int kw = idx & (KWORDS - 1);
        int g  = kw >> 3;               // group (8 words per 64-elem group)
        float s = sc[o * QGROUPS + g];
        uint32_t zw = qz[o * (QGROUPS / 8) + (g >> 3)];
        float zp = (float)((zw >> ((g & 7) * 4)) & 0xF);
        float c  = -s * zp;             // w = s*v + c; |w| <= 0.15, fp16-safe
        uint32_t w = qw[idx];
        __half2 h0 = __floats2half2_rn(fmaf(s, (float)((w      ) & 0xF), c),
                                       fmaf(s, (float)((w >>  4) & 0xF), c));
        __half2 h1 = __floats2half2_rn(fmaf(s, (float)((w >>  8) & 0xF), c),
                                       fmaf(s, (float)((w >> 12) & 0xF), c));
        __half2 h2 = __floats2half2_rn(fmaf(s, (float)((w >> 16) & 0xF), c),
                                       fmaf(s, (float)((w >> 20) & 0xF), c));
        __half2 h3 = __floats2half2_rn(fmaf(s, (float)((w >> 24) & 0xF), c),
                                       fmaf(s, (float)((w >> 28) & 0xF), c));
        uint4 o4;
        o4.x = *reinterpret_cast<uint32_t*>(&h0);
        o4.y = *reinterpret_cast<uint32_t*>(&h1);
        o4.z = *reinterpret_cast<uint32_t*>(&h2);
        o4.w = *reinterpret_cast<uint32_t*>(&h3);
        reinterpret_cast<uint4*>(g_Bh + (size_t)o * IN_F)[kw] = o4;
    }
}

// ---------------------------------------------------------------------------
// Persistent GEMM: mma.sync.m16n8k16 fp16 -> f32, CTA 64x128x64, 3 CTAs/SM.
// Each CTA walks tiles c, c+444, c+888, ... with a GLOBAL iteration counter:
// the cp.async lookahead (+2) crosses tile boundaries, so the pipeline never
// drains; the register-only epilogue overlaps the next tile's prologue loads.
// Tile index t -> (mt = t & 63, nt = t >> 6): M-fastest for L2 reuse of B.
// ---------------------------------------------------------------------------
__global__ void __launch_bounds__(NTHREADS, 3)
gemm_f16_kernel(const float* __restrict__ bias, float* __restrict__ out) {
    extern __shared__ __align__(1024) char smem[];
    const uint32_t sbase = smem_u32(smem);
    const int tid  = threadIdx.x;
    const int wid  = tid >> 5;
    const int lane = tid & 31;
    const int wm   = wid & 1;        // warp M coord (2)
    const int wn   = wid >> 1;       // warp N coord (2)
    const int c    = blockIdx.x;

    const int ntile = (NTILES - c + NCTAS - 1) / NCTAS;   // 13 or 12
    const int niter = ntile * NKIT;

    // Loader for global iteration li (tile-local index lt = li/64, kt = li%64).
    auto load_iter = [&](int li) {
        const int lt   = li >> 6;
        const int kt   = li & (NKIT - 1);
        const int tile = c + lt * NCTAS;
        const int m0   = (tile & (NMT - 1)) * BM;
        const int n0   = (tile >> 6) * BN;
        const int s    = li % NSTAGE;
        const uint32_t abuf = sbase + s * STAGE_BYTES;
        const uint32_t bbuf = abuf + A_STAGE_BYTES;
        const __half* Ag = g_Xh + (size_t)m0 * IN_F + kt * BK;
        const __half* Bg = g_Bh + (size_t)n0 * IN_F + kt * BK;
        #pragma unroll
        for (int j = 0; j < 4; j++) {
            int q = tid + j * NTHREADS;       // 0..511
            int r = q >> 3;                   // A row 0..63
            int ch = q & 7;                   // 16B chunk
            uint32_t off = (uint32_t)(r * 128 + ch * 16);
            uint32_t sw  = off ^ ((off >> 3) & 0x70);
            asm volatile("cp.async.cg.shared.global [%0], [%1], 16;"
                         :: "r"(abuf + sw), "l"(Ag + (size_t)r * IN_F + ch * 8)
                         : "memory");
        }
        #pragma unroll
        for (int j = 0; j < 8; j++) {
            int q = tid + j * NTHREADS;       // 0..1023
            int r = q >> 3;                   // B row 0..127
            int ch = q & 7;
            uint32_t off = (uint32_t)(r * 128 + ch * 16);
            uint32_t sw  = off ^ ((off >> 3) & 0x70);
            asm volatile("cp.async.cg.shared.global [%0], [%1], 16;"
                         :: "r"(bbuf + sw), "l"(Bg + (size_t)r * IN_F + ch * 8)
                         : "memory");
        }
    };

    // Prologue: iterations 0, 1
    load_iter(0);
    asm volatile("cp.async.commit_group;" ::: "memory");
    load_iter(1);
    asm volatile("cp.async.commit_group;" ::: "memory");

    const int lrow   = lane & 15;    // ldmatrix source row within 16
    const int lchunk = lane >> 4;    // 0: k0-7 chunk, 1: k8-15 chunk
    const int qrow   = lane >> 2;    // epilogue row 0..7
    const int qcol   = (lane & 3) * 2;

    float acc[2][8][4];

    for (int ct = 0; ct < ntile; ct++) {
        const int tile = c + ct * NCTAS;
        const int m0   = (tile & (NMT - 1)) * BM;
        const int n0   = (tile >> 6) * BN;

        #pragma unroll
        for (int mi = 0; mi < 2; mi++)
            #pragma unroll
            for (int nf = 0; nf < 8; nf++)
                #pragma unroll
                for (int e = 0; e < 4; e++) acc[mi][nf][e] = 0.0f;

        for (int kt = 0; kt < NKIT; kt++) {
            const int g = ct * NKIT + kt;     // global compute iteration
            asm volatile("cp.async.wait_group %0;" :: "n"(NSTAGE - 2) : "memory");
            __syncthreads();

            // Lookahead +2 (may belong to the next tile: pipeline never drains)
            const int li = g + NSTAGE - 1;
            if (li < niter) load_iter(li);
            asm volatile("cp.async.commit_group;" ::: "memory");

            const int s = g % NSTAGE;
            const uint32_t abuf = sbase + s * STAGE_BYTES;
            const uint32_t bbuf = abuf + A_STAGE_BYTES;

            #pragma unroll
            for (int k16 = 0; k16 < BK / 16; k16++) {
                uint32_t af[2][4], bf[4][4];
                const int chunk = k16 * 2 + lchunk;
                #pragma unroll
                for (int mi = 0; mi < 2; mi++) {
                    int row = wm * 32 + mi * 16 + lrow;
                    uint32_t off = (uint32_t)(row * 128 + chunk * 16);
                    ldsm_x4(abuf + (off ^ ((off >> 3) & 0x70)), af[mi]);
                }
                #pragma unroll
                for (int nj = 0; nj < 4; nj++) {
                    int row = wn * 64 + nj * 16 + lrow;
                    uint32_t off = (uint32_t)(row * 128 + chunk * 16);
                    ldsm_x4(bbuf + (off ^ ((off >> 3) & 0x70)), bf[nj]);
                }
                #pragma unroll
                for (int mi = 0; mi < 2; mi++)
                    #pragma unroll
                    for (int nj = 0; nj < 4; nj++) {
                        mma16816(acc[mi][2 * nj],     af[mi],
                                 bf[nj][0], bf[nj][2]);
                        mma16816(acc[mi][2 * nj + 1], af[mi],
                                 bf[nj][1], bf[nj][3]);
                    }
            }
        }

        // Epilogue (register-only source; overlaps next tile's in-flight loads)
        #pragma unroll
        for (int mi = 0; mi < 2; mi++) {
            int gr = m0 + wm * 32 + mi * 16 + qrow;
            float* p0 = out + (size_t)gr * OUT_F;
            float* p1 = p0 + 8 * OUT_F;
            #pragma unroll
            for (int nf = 0; nf < 8; nf++) {
                int col = n0 + wn * 64 + nf * 8 + qcol;
                float bx = __ldg(bias + col);
                float by = __ldg(bias + col + 1);
                float2 v0, v1;
                v0.x = acc[mi][nf][0] + bx;
                v0.y = acc[mi][nf][1] + by;
                v1.x = acc[mi][nf][2] + bx;
                v1.y = acc[mi][nf][3] + by;
                *reinterpret_cast<float2*>(p0 + col) = v0;
                *reinterpret_cast<float2*>(p1 + col) = v1;
            }
        }
    }
}

// ---------------------------------------------------------------------------
extern "C" void kernel_launch(void* const* d_in, const int* in_sizes, int n_in,
                              void* d_out, int out_size) {
    const float*    x    = (const float*)   d_in[0];
    const uint32_t* qw   = (const uint32_t*)d_in[1];
    const uint32_t* qz   = (const uint32_t*)d_in[2];
    const float*    sc   = (const float*)   d_in[3];
    const float*    bias = (const float*)   d_in[4];
    float*          out  = (float*)d_out;

    // 1) fused: x -> fp16  ||  int4 dequant -> fp16 (concurrent)
    prep_kernel<<<NCONV_BLKS + NDEQ_BLKS, 256>>>((const float4*)x, qw, qz, sc);

    // 2) persistent fp16 mma.sync GEMM, 3 CTAs/SM, cross-tile pipeline
    cudaFuncSetAttribute(gemm_f16_kernel,
                         cudaFuncAttributeMaxDynamicSharedMemorySize, SMEM_TOTAL);
    gemm_f16_kernel<<<NCTAS, NTHREADS, SMEM_TOTAL>>>(bias, out);
}

// round 11
// speedup vs baseline: 1.1386x; 1.1386x over previous
#include <cuda_runtime.h>
#include <cuda_fp16.h>
#include <cstdint>

// Problem constants
#define TOKENS   4096
#define IN_F     4096
#define OUT_F    11008
#define QGROUPS  64
#define KWORDS   (IN_F / 8)       // 512 packed int32 per output row

// GEMM tiling: 64x128 CTA, BK=32, 4-stage, 4 CTAs/SM (16 warps/SM).
#define BM       64
#define BN       128
#define BK       32               // fp16 elements per stage along K (64B rows)
#define NSTAGE   4
#define NKIT     (IN_F / BK)      // 128
#define NTHREADS 128              // 4 warps, 2x2 grid of 32x64 warp tiles
#define A_STAGE_BYTES (BM * BK * 2)               // 4096
#define B_STAGE_BYTES (BN * BK * 2)               // 8192
#define STAGE_BYTES   (A_STAGE_BYTES + B_STAGE_BYTES)  // 12288
#define SMEM_TOTAL    (NSTAGE * STAGE_BYTES)      // 49152 (4 CTAs -> 192KB/SM)

#define NMT      (TOKENS / BM)    // 64 M tiles
#define NNT      (OUT_F / BN)     // 86 N tiles

// Scratch (device globals: allocation-free rule)
__device__ __half g_Bh[(size_t)OUT_F * IN_F];   // dequantized fp16 weights
__device__ __half g_Xh[(size_t)TOKENS * IN_F];  // fp16 activations

// ---------------------------------------------------------------------------
// Helpers
// ---------------------------------------------------------------------------
__device__ __forceinline__ uint32_t smem_u32(const void* p) {
    uint32_t a;
    asm("{ .reg .u64 t; cvta.to.shared.u64 t, %1; cvt.u32.u64 %0, t; }"
        : "=r"(a) : "l"(p));
    return a;
}

// SW64 swizzle for 64-byte rows: XOR 16B-chunk-select bits [5:4] with row
// bits [8:7]. Conflict-free for ldmatrix (8 rows -> 8 distinct 16B granules)
// and for the cp.async store pattern below.
#define SW64(off) ((off) ^ (((off) >> 3) & 0x30))

__device__ __forceinline__ void ldsm_x4(uint32_t addr, uint32_t* r) {
    asm volatile("ldmatrix.sync.aligned.m8n8.x4.shared.b16 {%0,%1,%2,%3}, [%4];"
                 : "=r"(r[0]), "=r"(r[1]), "=r"(r[2]), "=r"(r[3]) : "r"(addr));
}

__device__ __forceinline__ void mma16816(float* c, const uint32_t* a,
                                         uint32_t b0, uint32_t b1) {
    asm volatile(
        "mma.sync.aligned.m16n8k16.row.col.f32.f16.f16.f32 "
        "{%0,%1,%2,%3}, {%4,%5,%6,%7}, {%8,%9}, {%0,%1,%2,%3};"
        : "+f"(c[0]), "+f"(c[1]), "+f"(c[2]), "+f"(c[3])
        : "r"(a[0]), "r"(a[1]), "r"(a[2]), "r"(a[3]), "r"(b0), "r"(b1));
}

// ---------------------------------------------------------------------------
// Fused pre-kernel: blocks [0, NCONV_BLKS) convert x -> fp16; the rest
// dequantize int4 weights -> fp16. Independent jobs, run concurrently.
// fp16 mantissa step = 2^-11 -> output rel_err ~2.7e-4 < 1e-3.
// ---------------------------------------------------------------------------
#define NCONV_ELEMS (TOKENS * IN_F / 8)           // uint4 stores: 2097152
#define NCONV_BLKS  ((NCONV_ELEMS + 255) / 256)   // 8192
#define NDEQ_ELEMS  (OUT_F * KWORDS)              // 5636096
#define NDEQ_BLKS   ((NDEQ_ELEMS + 255) / 256)    // 22016

__global__ void prep_kernel(const float4* __restrict__ x,
                            const uint32_t* __restrict__ qw,
                            const uint32_t* __restrict__ qz,
                            const float* __restrict__ sc) {
    if (blockIdx.x < NCONV_BLKS) {
        int i = blockIdx.x * 256 + threadIdx.x;
        if (i >= NCONV_ELEMS) return;
        float4 a = x[2 * i];
        float4 b = x[2 * i + 1];
        __half2 h0 = __floats2half2_rn(a.x, a.y);
        __half2 h1 = __floats2half2_rn(a.z, a.w);
        __half2 h2 = __floats2half2_rn(b.x, b.y);
        __half2 h3 = __floats2half2_rn(b.z, b.w);
        uint4 o;
        o.x = *reinterpret_cast<uint32_t*>(&h0);
        o.y = *reinterpret_cast<uint32_t*>(&h1);
        o.z = *reinterpret_cast<uint32_t*>(&h2);
        o.w = *reinterpret_cast<uint32_t*>(&h3);
        reinterpret_cast<uint4*>(g_Xh)[i] = o;
    } else {
        int idx = (blockIdx.x - NCONV_BLKS) * 256 + threadIdx.x;
        if (idx >= NDEQ_ELEMS) return;
        int o  = idx >> 9;              // / 512
        int kw = idx & (KWORDS - 1);
        int g  = kw >> 3;               // group (8 words per 64-elem group)
        float s = sc[o * QGROUPS + g];
        uint32_t zw = qz[o * (QGROUPS / 8) + (g >> 3)];
        float zp = (float)((zw >> ((g & 7) * 4)) & 0xF);
        float c  = -s * zp;             // w = s*v + c; |w| <= 0.15, fp16-safe
        uint32_t w = qw[idx];
        __half2 h0 = __floats2half2_rn(fmaf(s, (float)((w      ) & 0xF), c),
                                       fmaf(s, (float)((w >>  4) & 0xF), c));
        __half2 h1 = __floats2half2_rn(fmaf(s, (float)((w >>  8) & 0xF), c),
                                       fmaf(s, (float)((w >> 12) & 0xF), c));
        __half2 h2 = __floats2half2_rn(fmaf(s, (float)((w >> 16) & 0xF), c),
                                       fmaf(s, (float)((w >> 20) & 0xF), c));
        __half2 h3 = __floats2half2_rn(fmaf(s, (float)((w >> 24) & 0xF), c),
                                       fmaf(s, (float)((w >> 28) & 0xF), c));
        uint4 o4;
        o4.x = *reinterpret_cast<uint32_t*>(&h0);
        o4.y = *reinterpret_cast<uint32_t*>(&h1);
        o4.z = *reinterpret_cast<uint32_t*>(&h2);
        o4.w = *reinterpret_cast<uint32_t*>(&h3);
        reinterpret_cast<uint4*>(g_Bh + (size_t)o * IN_F)[kw] = o4;
    }
}

// ---------------------------------------------------------------------------
// Main GEMM: mma.sync.m16n8k16 fp16 -> f32, CTA 64x128x32, 4-stage cp.async,
// 4 CTAs per SM (16 warps/SM = 4 per SMSP for latency coverage).
// 4 warps in 2(M) x 2(N) grid; warp tile 32x64.
// Smem: K-major 64B rows, SW64 swizzle -> conflict-free ldmatrix + stores.
// ---------------------------------------------------------------------------
__global__ void __launch_bounds__(NTHREADS, 4)
gemm_f16_kernel(const float* __restrict__ bias, float* __restrict__ out) {
    extern __shared__ __align__(1024) char smem[];
    const uint32_t sbase = smem_u32(smem);
    const int tid  = threadIdx.x;
    const int wid  = tid >> 5;
    const int lane = tid & 31;
    const int wm   = wid & 1;        // warp M coord (2)
    const int wn   = wid >> 1;       // warp N coord (2)

    // M-fastest CTA order: concurrent CTAs share B bands; A stays L2-resident.
    const int mt = blockIdx.x & (NMT - 1);  // 64 M tiles
    const int nt = blockIdx.x >> 6;         // 86 N tiles
    const int m0 = mt * BM;
    const int n0 = nt * BN;

    const __half* Abase = g_Xh + (size_t)m0 * IN_F;
    const __half* Bbase = g_Bh + (size_t)n0 * IN_F;

    // Stage loader: A 256 chunks of 16B (2/thread), B 512 chunks (4/thread).
    auto load_stage = [&](int s, int kl) {
        const int k0 = kl * BK;
        const uint32_t abuf = sbase + s * STAGE_BYTES;
        const uint32_t bbuf = abuf + A_STAGE_BYTES;
        const __half* Ag = Abase + k0;
        const __half* Bg = Bbase + k0;
        #pragma unroll
        for (int j = 0; j < 2; j++) {
            int q  = tid + j * NTHREADS;      // 0..255
            int r  = q >> 2;                  // A row 0..63
            int ch = q & 3;                   // 16B chunk 0..3
            uint32_t off = (uint32_t)(r * 64 + ch * 16);
            asm volatile("cp.async.cg.shared.global [%0], [%1], 16;"
                         :: "r"(abuf + SW64(off)),
                            "l"(Ag + (size_t)r * IN_F + ch * 8) : "memory");
        }
        #pragma unroll
        for (int j = 0; j < 4; j++) {
            int q  = tid + j * NTHREADS;      // 0..511
            int r  = q >> 2;                  // B row 0..127
            int ch = q & 3;
            uint32_t off = (uint32_t)(r * 64 + ch * 16);
            asm volatile("cp.async.cg.shared.global [%0], [%1], 16;"
                         :: "r"(bbuf + SW64(off)),
                            "l"(Bg + (size_t)r * IN_F + ch * 8) : "memory");
        }
    };

    // Prologue: fill NSTAGE-1 stages
    #pragma unroll
    for (int kl = 0; kl < NSTAGE - 1; kl++) {
        load_stage(kl, kl);
        asm volatile("cp.async.commit_group;" ::: "memory");
    }

    float acc[2][8][4];
    #pragma unroll
    for (int mi = 0; mi < 2; mi++)
        #pragma unroll
        for (int nf = 0; nf < 8; nf++)
            #pragma unroll
            for (int e = 0; e < 4; e++) acc[mi][nf][e] = 0.0f;

    const int lrow   = lane & 15;    // ldmatrix source row within 16
    const int lchunk = lane >> 4;    // 0: k0-7 chunk, 1: k8-15 chunk

    for (int kt = 0; kt < NKIT; kt++) {
        asm volatile("cp.async.wait_group %0;" :: "n"(NSTAGE - 2) : "memory");
        __syncthreads();

        // Prefetch stage kt+NSTAGE-1 (its buffer was consumed at kt-1; all
        // warps passed the barrier above, so it is free).
        const int kl = kt + NSTAGE - 1;
        if (kl < NKIT) load_stage(kl & (NSTAGE - 1), kl);
        asm volatile("cp.async.commit_group;" ::: "memory");

        // Compute on stage s (power-of-2 stage index: cheap).
        const int s = kt & (NSTAGE - 1);
        const uint32_t abuf = sbase + s * STAGE_BYTES;
        const uint32_t bbuf = abuf + A_STAGE_BYTES;

        #pragma unroll
        for (int k16 = 0; k16 < BK / 16; k16++) {
            uint32_t af[2][4], bf[4][4];
            const int chunk = k16 * 2 + lchunk;   // 0..3
            #pragma unroll
            for (int mi = 0; mi < 2; mi++) {
                int row = wm * 32 + mi * 16 + lrow;
                uint32_t off = (uint32_t)(row * 64 + chunk * 16);
                ldsm_x4(abuf + SW64(off), af[mi]);
            }
            #pragma unroll
            for (int nj = 0; nj < 4; nj++) {
                int row = wn * 64 + nj * 16 + lrow;
                uint32_t off = (uint32_t)(row * 64 + chunk * 16);
                ldsm_x4(bbuf + SW64(off), bf[nj]);
            }
            #pragma unroll
            for (int mi = 0; mi < 2; mi++)
                #pragma unroll
                for (int nj = 0; nj < 4; nj++) {
                    mma16816(acc[mi][2 * nj],     af[mi], bf[nj][0], bf[nj][2]);
                    mma16816(acc[mi][2 * nj + 1], af[mi], bf[nj][1], bf[nj][3]);
                }
        }
    }

    // Epilogue: fragment layout c0,c1 -> (row=q, col=2c..2c+1), c2,c3 -> row+8.
    const int qrow = lane >> 2;          // 0..7
    const int qcol = (lane & 3) * 2;
    #pragma unroll
    for (int mi = 0; mi < 2; mi++) {
        int gr = m0 + wm * 32 + mi * 16 + qrow;
        float* p0 = out + (size_t)gr * OUT_F;
        float* p1 = p0 + 8 * OUT_F;
        #pragma unroll
        for (int nf = 0; nf < 8; nf++) {
            int col = n0 + wn * 64 + nf * 8 + qcol;
            float bx = __ldg(bias + col);
            float by = __ldg(bias + col + 1);
            float2 v0, v1;
            v0.x = acc[mi][nf][0] + bx;
            v0.y = acc[mi][nf][1] + by;
            v1.x = acc[mi][nf][2] + bx;
            v1.y = acc[mi][nf][3] + by;
            *reinterpret_cast<float2*>(p0 + col) = v0;
            *reinterpret_cast<float2*>(p1 + col) = v1;
        }
    }
}

// ---------------------------------------------------------------------------
extern "C" void kernel_launch(void* const* d_in, const int* in_sizes, int n_in,
                              void* d_out, int out_size) {
    const float*    x    = (const float*)   d_in[0];
    const uint32_t* qw   = (const uint32_t*)d_in[1];
    const uint32_t* qz   = (const uint32_t*)d_in[2];
    const float*    sc   = (const float*)   d_in[3];
    const float*    bias = (const float*)   d_in[4];
    float*          out  = (float*)d_out;

    // 1) fused: x -> fp16  ||  int4 dequant -> fp16 (concurrent)
    prep_kernel<<<NCONV_BLKS + NDEQ_BLKS, 256>>>((const float4*)x, qw, qz, sc);

    // 2) fp16 mma.sync GEMM, 4 CTAs/SM, 64x128 tiles, BK=32, 4 stages
    cudaFuncSetAttribute(gemm_f16_kernel,
                         cudaFuncAttributeMaxDynamicSharedMemorySize, SMEM_TOTAL);
    dim3 grid(NMT * NNT);  // 64 * 86 = 5504, M-fastest
    gemm_f16_kernel<<<grid, NTHREADS, SMEM_TOTAL>>>(bias, out);
}

// round 12
// speedup vs baseline: 1.1729x; 1.0302x over previous
#include <cuda_runtime.h>
#include <cuda_fp16.h>
#include <cstdint>

// Problem constants
#define TOKENS   4096
#define IN_F     4096
#define OUT_F    11008
#define QGROUPS  64
#define KWORDS   (IN_F / 8)       // 512 packed int32 per output row

// GEMM tiling: the measured issue-ceiling config (R8).
#define BM       64
#define BN       128
#define BK       64               // fp16 elements per stage along K (128B rows)
#define NSTAGE   3
#define NKIT     (IN_F / BK)      // 64
#define NTHREADS 128              // 4 warps, 2x2 grid of 32x64 warp tiles
#define A_STAGE_BYTES (BM * BK * 2)               // 8192
#define B_STAGE_BYTES (BN * BK * 2)               // 16384
#define STAGE_BYTES   (A_STAGE_BYTES + B_STAGE_BYTES)  // 24576
#define SMEM_TOTAL    (NSTAGE * STAGE_BYTES)      // 73728 (3 CTAs -> 216KB/SM)

#define NMT      (TOKENS / BM)    // 64 M tiles
#define NNT      (OUT_F / BN)     // 86 N tiles

// Scratch (device globals: allocation-free rule)
__device__ __half g_Bh[(size_t)OUT_F * IN_F];   // dequantized fp16 weights
__device__ __half g_Xh[(size_t)TOKENS * IN_F];  // fp16 activations

// ---------------------------------------------------------------------------
// Helpers
// ---------------------------------------------------------------------------
__device__ __forceinline__ uint32_t smem_u32(const void* p) {
    uint32_t a;
    asm("{ .reg .u64 t; cvta.to.shared.u64 t, %1; cvt.u32.u64 %0, t; }"
        : "=r"(a) : "l"(p));
    return a;
}

__device__ __forceinline__ void ldsm_x4(uint32_t addr, uint32_t* r) {
    asm volatile("ldmatrix.sync.aligned.m8n8.x4.shared.b16 {%0,%1,%2,%3}, [%4];"
                 : "=r"(r[0]), "=r"(r[1]), "=r"(r[2]), "=r"(r[3]) : "r"(addr));
}

__device__ __forceinline__ void mma16816(float* c, const uint32_t* a,
                                         uint32_t b0, uint32_t b1) {
    asm volatile(
        "mma.sync.aligned.m16n8k16.row.col.f32.f16.f16.f32 "
        "{%0,%1,%2,%3}, {%4,%5,%6,%7}, {%8,%9}, {%0,%1,%2,%3};"
        : "+f"(c[0]), "+f"(c[1]), "+f"(c[2]), "+f"(c[3])
        : "r"(a[0]), "r"(a[1]), "r"(a[2]), "r"(a[3]), "r"(b0), "r"(b1));
}

// ---------------------------------------------------------------------------
// Fused pre-kernel: blocks [0, NCONV_BLKS) convert x -> fp16; the rest
// dequantize int4 weights -> fp16. Independent jobs, run concurrently.
// fp16 mantissa step = 2^-11 -> output rel_err ~2.7e-4 < 1e-3.
// ---------------------------------------------------------------------------
#define NCONV_ELEMS (TOKENS * IN_F / 8)           // uint4 stores: 2097152
#define NCONV_BLKS  ((NCONV_ELEMS + 255) / 256)   // 8192
#define NDEQ_ELEMS  (OUT_F * KWORDS)              // 5636096
#define NDEQ_BLKS   ((NDEQ_ELEMS + 255) / 256)    // 22016

__global__ void prep_kernel(const float4* __restrict__ x,
                            const uint32_t* __restrict__ qw,
                            const uint32_t* __restrict__ qz,
                            const float* __restrict__ sc) {
    if (blockIdx.x < NCONV_BLKS) {
        int i = blockIdx.x * 256 + threadIdx.x;
        if (i >= NCONV_ELEMS) return;
        float4 a = x[2 * i];
        float4 b = x[2 * i + 1];
        __half2 h0 = __floats2half2_rn(a.x, a.y);
        __half2 h1 = __floats2half2_rn(a.z, a.w);
        __half2 h2 = __floats2half2_rn(b.x, b.y);
        __half2 h3 = __floats2half2_rn(b.z, b.w);
        uint4 o;
        o.x = *reinterpret_cast<uint32_t*>(&h0);
        o.y = *reinterpret_cast<uint32_t*>(&h1);
        o.z = *reinterpret_cast<uint32_t*>(&h2);
        o.w = *reinterpret_cast<uint32_t*>(&h3);
        reinterpret_cast<uint4*>(g_Xh)[i] = o;
    } else {
        int idx = (blockIdx.x - NCONV_BLKS) * 256 + threadIdx.x;
        if (idx >= NDEQ_ELEMS) return;
        int o  = idx >> 9;              // / 512
        int kw = idx & (KWORDS - 1);
        int g  = kw >> 3;               // group (8 words per 64-elem group)
        float s = sc[o * QGROUPS + g];
        uint32_t zw = qz[o * (QGROUPS / 8) + (g >> 3)];
        float zp = (float)((zw >> ((g & 7) * 4)) & 0xF);
        float c  = -s * zp;             // w = s*v + c; |w| <= 0.15, fp16-safe
        uint32_t w = qw[idx];
        __half2 h0 = __floats2half2_rn(fmaf(s, (float)((w      ) & 0xF), c),
                                       fmaf(s, (float)((w >>  4) & 0xF), c));
        __half2 h1 = __floats2half2_rn(fmaf(s, (float)((w >>  8) & 0xF), c),
                                       fmaf(s, (float)((w >> 12) & 0xF), c));
        __half2 h2 = __floats2half2_rn(fmaf(s, (float)((w >> 16) & 0xF), c),
                                       fmaf(s, (float)((w >> 20) & 0xF), c));
        __half2 h3 = __floats2half2_rn(fmaf(s, (float)((w >> 24) & 0xF), c),
                                       fmaf(s, (float)((w >> 28) & 0xF), c));
        uint4 o4;
        o4.x = *reinterpret_cast<uint32_t*>(&h0);
        o4.y = *reinterpret_cast<uint32_t*>(&h1);
        o4.z = *reinterpret_cast<uint32_t*>(&h2);
        o4.w = *reinterpret_cast<uint32_t*>(&h3);
        reinterpret_cast<uint4*>(g_Bh + (size_t)o * IN_F)[kw] = o4;
    }
}

// ---------------------------------------------------------------------------
// Main GEMM: mma.sync.m16n8k16 fp16 -> f32, CTA 64x128x64, 3-stage cp.async,
// 3 CTAs per SM. 4 warps in 2(M) x 2(N) grid; warp tile 32x64.
// Smem: K-major 128B rows, SW128 swizzle -> conflict-free ldmatrix.
// This config measured at ~99% of the legacy-HMMA issue ceiling (rt~12/SMSP).
// ---------------------------------------------------------------------------
__global__ void __launch_bounds__(NTHREADS, 3)
gemm_f16_kernel(const float* __restrict__ bias, float* __restrict__ out) {
    extern __shared__ __align__(1024) char smem[];
    const uint32_t sbase = smem_u32(smem);
    const int tid  = threadIdx.x;
    const int wid  = tid >> 5;
    const int lane = tid & 31;
    const int wm   = wid & 1;        // warp M coord (2)
    const int wn   = wid >> 1;       // warp N coord (2)

    // M-fastest CTA order: concurrent CTAs share B bands; A stays L2-resident.
    const int mt = blockIdx.x & (NMT - 1);  // 64 M tiles
    const int nt = blockIdx.x >> 6;         // 86 N tiles
    const int m0 = mt * BM;
    const int n0 = nt * BN;

    const __half* Abase = g_Xh + (size_t)m0 * IN_F;
    const __half* Bbase = g_Bh + (size_t)n0 * IN_F;

    // Stage loader: A 512 chunks of 16B (4/thread), B 1024 chunks (8/thread).
    auto load_stage = [&](int s, int kl) {
        const int k0 = kl * BK;
        const uint32_t abuf = sbase + s * STAGE_BYTES;
        const uint32_t bbuf = abuf + A_STAGE_BYTES;
        const __half* Ag = Abase + k0;
        const __half* Bg = Bbase + k0;
        #pragma unroll
        for (int j = 0; j < 4; j++) {
            int q = tid + j * NTHREADS;       // 0..511
            int r = q >> 3;                   // A row 0..63
            int c = q & 7;                    // 16B chunk 0..7
            uint32_t off = (uint32_t)(r * 128 + c * 16);
            uint32_t sw  = off ^ ((off >> 3) & 0x70);
            asm volatile("cp.async.cg.shared.global [%0], [%1], 16;"
                         :: "r"(abuf + sw), "l"(Ag + (size_t)r * IN_F + c * 8)
                         : "memory");
        }
        #pragma unroll
        for (int j = 0; j < 8; j++) {
            int q = tid + j * NTHREADS;       // 0..1023
            int r = q >> 3;                   // B row 0..127
            int c = q & 7;
            uint32_t off = (uint32_t)(r * 128 + c * 16);
            uint32_t sw  = off ^ ((off >> 3) & 0x70);
            asm volatile("cp.async.cg.shared.global [%0], [%1], 16;"
                         :: "r"(bbuf + sw), "l"(Bg + (size_t)r * IN_F + c * 8)
                         : "memory");
        }
    };

    // Prologue: fill NSTAGE-1 stages
    #pragma unroll
    for (int kl = 0; kl < NSTAGE - 1; kl++) {
        load_stage(kl, kl);
        asm volatile("cp.async.commit_group;" ::: "memory");
    }

    float acc[2][8][4];
    #pragma unroll
    for (int mi = 0; mi < 2; mi++)
        #pragma unroll
        for (int nf = 0; nf < 8; nf++)
            #pragma unroll
            for (int e = 0; e < 4; e++) acc[mi][nf][e] = 0.0f;

    const int lrow   = lane & 15;    // ldmatrix source row within 16
    const int lchunk = lane >> 4;    // 0: k0-7 chunk, 1: k8-15 chunk

    for (int kt = 0; kt < NKIT; kt++) {
        asm volatile("cp.async.wait_group %0;" :: "n"(NSTAGE - 2) : "memory");
        __syncthreads();

        // Prefetch stage kt+NSTAGE-1 (its buffer was consumed at kt-1; all
        // warps passed the barrier above, so it is free).
        const int kl = kt + NSTAGE - 1;
        if (kl < NKIT) load_stage(kl % NSTAGE, kl);
        asm volatile("cp.async.commit_group;" ::: "memory");

        // Compute on stage s.
        const int s = kt % NSTAGE;
        const uint32_t abuf = sbase + s * STAGE_BYTES;
        const uint32_t bbuf = abuf + A_STAGE_BYTES;

        #pragma unroll
        for (int k16 = 0; k16 < BK / 16; k16++) {
            uint32_t af[2][4], bf[4][4];
            const int chunk = k16 * 2 + lchunk;
            #pragma unroll
            for (int mi = 0; mi < 2; mi++) {
                int row = wm * 32 + mi * 16 + lrow;
                uint32_t off = (uint32_t)(row * 128 + chunk * 16);
                ldsm_x4(abuf + (off ^ ((off >> 3) & 0x70)), af[mi]);
            }
            #pragma unroll
            for (int nj = 0; nj < 4; nj++) {
                int row = wn * 64 + nj * 16 + lrow;
                uint32_t off = (uint32_t)(row * 128 + chunk * 16);
                ldsm_x4(bbuf + (off ^ ((off >> 3) & 0x70)), bf[nj]);
            }
            #pragma unroll
            for (int mi = 0; mi < 2; mi++)
                #pragma unroll
                for (int nj = 0; nj < 4; nj++) {
                    mma16816(acc[mi][2 * nj],     af[mi], bf[nj][0], bf[nj][2]);
                    mma16816(acc[mi][2 * nj + 1], af[mi], bf[nj][1], bf[nj][3]);
                }
        }
    }

    // Epilogue: fragment layout c0,c1 -> (row=q, col=2c..2c+1), c2,c3 -> row+8.
    const int qrow = lane >> 2;          // 0..7
    const int qcol = (lane & 3) * 2;
    #pragma unroll
    for (int mi = 0; mi < 2; mi++) {
        int gr = m0 + wm * 32 + mi * 16 + qrow;
        float* p0 = out + (size_t)gr * OUT_F;
        float* p1 = p0 + 8 * OUT_F;
        #pragma unroll
        for (int nf = 0; nf < 8; nf++) {
            int col = n0 + wn * 64 + nf * 8 + qcol;
            float bx = __ldg(bias + col);
            float by = __ldg(bias + col + 1);
            float2 v0, v1;
            v0.x = acc[mi][nf][0] + bx;
            v0.y = acc[mi][nf][1] + by;
            v1.x = acc[mi][nf][2] + bx;
            v1.y = acc[mi][nf][3] + by;
            *reinterpret_cast<float2*>(p0 + col) = v0;
            *reinterpret_cast<float2*>(p1 + col) = v1;
        }
    }
}

// ---------------------------------------------------------------------------
extern "C" void kernel_launch(void* const* d_in, const int* in_sizes, int n_in,
                              void* d_out, int out_size) {
    const float*    x    = (const float*)   d_in[0];
    const uint32_t* qw   = (const uint32_t*)d_in[1];
    const uint32_t* qz   = (const uint32_t*)d_in[2];
    const float*    sc   = (const float*)   d_in[3];
    const float*    bias = (const float*)   d_in[4];
    float*          out  = (float*)d_out;

    // 1) fused: x -> fp16  ||  int4 dequant -> fp16 (concurrent)
    prep_kernel<<<NCONV_BLKS + NDEQ_BLKS, 256>>>((const float4*)x, qw, qz, sc);

    // 2) fp16 mma.sync GEMM, 3 CTAs/SM, 64x128 tiles, BK=64, 3 stages
    cudaFuncSetAttribute(gemm_f16_kernel,
                         cudaFuncAttributeMaxDynamicSharedMemorySize, SMEM_TOTAL);
    dim3 grid(NMT * NNT);  // 64 * 86 = 5504, M-fastest
    gemm_f16_kernel<<<grid, NTHREADS, SMEM_TOTAL>>>(bias, out);
}

// round 13
// speedup vs baseline: 1.2721x; 1.0846x over previous
#include <cuda_runtime.h>
#include <cuda_fp16.h>
#include <cstdint>

// Problem constants
#define TOKENS   4096
#define IN_F     4096
#define OUT_F    11008
#define QGROUPS  64
#define KWORDS   (IN_F / 8)       // 512 packed int32 per output row

// GEMM tiling: 64x128x64, 2-stage, 4 CTAs/SM (16 warps/SM, full BK).
#define BM       64
#define BN       128
#define BK       64               // fp16 elements per stage along K (128B rows)
#define NSTAGE   2
#define NKIT     (IN_F / BK)      // 64
#define NTHREADS 128              // 4 warps, 2x2 grid of 32x64 warp tiles
#define A_STAGE_BYTES (BM * BK * 2)               // 8192
#define B_STAGE_BYTES (BN * BK * 2)               // 16384
#define STAGE_BYTES   (A_STAGE_BYTES + B_STAGE_BYTES)  // 24576
#define SMEM_TOTAL    (NSTAGE * STAGE_BYTES)      // 49152 (4 CTAs -> 192KB/SM)

#define NMT      (TOKENS / BM)    // 64 M tiles
#define NNT      (OUT_F / BN)     // 86 N tiles

// Scratch (device globals: allocation-free rule)
__device__ __half g_Bh[(size_t)OUT_F * IN_F];   // dequantized fp16 weights
__device__ __half g_Xh[(size_t)TOKENS * IN_F];  // fp16 activations

// ---------------------------------------------------------------------------
// Helpers
// ---------------------------------------------------------------------------
__device__ __forceinline__ uint32_t smem_u32(const void* p) {
    uint32_t a;
    asm("{ .reg .u64 t; cvta.to.shared.u64 t, %1; cvt.u32.u64 %0, t; }"
        : "=r"(a) : "l"(p));
    return a;
}

__device__ __forceinline__ void ldsm_x4(uint32_t addr, uint32_t* r) {
    asm volatile("ldmatrix.sync.aligned.m8n8.x4.shared.b16 {%0,%1,%2,%3}, [%4];"
                 : "=r"(r[0]), "=r"(r[1]), "=r"(r[2]), "=r"(r[3]) : "r"(addr));
}

__device__ __forceinline__ void mma16816(float* c, const uint32_t* a,
                                         uint32_t b0, uint32_t b1) {
    asm volatile(
        "mma.sync.aligned.m16n8k16.row.col.f32.f16.f16.f32 "
        "{%0,%1,%2,%3}, {%4,%5,%6,%7}, {%8,%9}, {%0,%1,%2,%3};"
        : "+f"(c[0]), "+f"(c[1]), "+f"(c[2]), "+f"(c[3])
        : "r"(a[0]), "r"(a[1]), "r"(a[2]), "r"(a[3]), "r"(b0), "r"(b1));
}

// ---------------------------------------------------------------------------
// Fused pre-kernel: blocks [0, NCONV_BLKS) convert x -> fp16; the rest
// dequantize int4 weights -> fp16. Independent jobs, run concurrently.
// fp16 mantissa step = 2^-11 -> output rel_err ~2.7e-4 < 1e-3.
// ---------------------------------------------------------------------------
#define NCONV_ELEMS (TOKENS * IN_F / 8)           // uint4 stores: 2097152
#define NCONV_BLKS  ((NCONV_ELEMS + 255) / 256)   // 8192
#define NDEQ_ELEMS  (OUT_F * KWORDS)              // 5636096
#define NDEQ_BLKS   ((NDEQ_ELEMS + 255) / 256)    // 22016

__global__ void prep_kernel(const float4* __restrict__ x,
                            const uint32_t* __restrict__ qw,
                            const uint32_t* __restrict__ qz,
                            const float* __restrict__ sc) {
    if (blockIdx.x < NCONV_BLKS) {
        int i = blockIdx.x * 256 + threadIdx.x;
        if (i >= NCONV_ELEMS) return;
        float4 a = x[2 * i];
        float4 b = x[2 * i + 1];
        __half2 h0 = __floats2half2_rn(a.x, a.y);
        __half2 h1 = __floats2half2_rn(a.z, a.w);
        __half2 h2 = __floats2half2_rn(b.x, b.y);
        __half2 h3 = __floats2half2_rn(b.z, b.w);
        uint4 o;
        o.x = *reinterpret_cast<uint32_t*>(&h0);
        o.y = *reinterpret_cast<uint32_t*>(&h1);
        o.z = *reinterpret_cast<uint32_t*>(&h2);
        o.w = *reinterpret_cast<uint32_t*>(&h3);
        reinterpret_cast<uint4*>(g_Xh)[i] = o;
    } else {
        int idx = (blockIdx.x - NCONV_BLKS) * 256 + threadIdx.x;
        if (idx >= NDEQ_ELEMS) return;
        int o  = idx >> 9;              // / 512
        int kw = idx & (KWORDS - 1);
        int g  = kw >> 3;               // group (8 words per 64-elem group)
        float s = sc[o * QGROUPS + g];
        uint32_t zw = qz[o * (QGROUPS / 8) + (g >> 3)];
        float zp = (float)((zw >> ((g & 7) * 4)) & 0xF);
        float c  = -s * zp;             // w = s*v + c; |w| <= 0.15, fp16-safe
        uint32_t w = qw[idx];
        __half2 h0 = __floats2half2_rn(fmaf(s, (float)((w      ) & 0xF), c),
                                       fmaf(s, (float)((w >>  4) & 0xF), c));
        __half2 h1 = __floats2half2_rn(fmaf(s, (float)((w >>  8) & 0xF), c),
                                       fmaf(s, (float)((w >> 12) & 0xF), c));
        __half2 h2 = __floats2half2_rn(fmaf(s, (float)((w >> 16) & 0xF), c),
                                       fmaf(s, (float)((w >> 20) & 0xF), c));
        __half2 h3 = __floats2half2_rn(fmaf(s, (float)((w >> 24) & 0xF), c),
                                       fmaf(s, (float)((w >> 28) & 0xF), c));
        uint4 o4;
        o4.x = *reinterpret_cast<uint32_t*>(&h0);
        o4.y = *reinterpret_cast<uint32_t*>(&h1);
        o4.z = *reinterpret_cast<uint32_t*>(&h2);
        o4.w = *reinterpret_cast<uint32_t*>(&h3);
        reinterpret_cast<uint4*>(g_Bh + (size_t)o * IN_F)[kw] = o4;
    }
}

// ---------------------------------------------------------------------------
// Main GEMM: mma.sync.m16n8k16 fp16 -> f32, CTA 64x128x64, 2-stage cp.async,
// 4 CTAs per SM (16 warps/SM = 4 per SMSP). Loads for kt+1 are issued before
// kt's compute block and complete under its ~1500 cycles; 4 desynchronized
// CTAs per SM average out the L2 jitter a shallow pipeline exposes.
// 4 warps in 2(M) x 2(N) grid; warp tile 32x64.
// Smem: K-major 128B rows, SW128 swizzle -> conflict-free ldmatrix.
// ---------------------------------------------------------------------------
__global__ void __launch_bounds__(NTHREADS, 4)
gemm_f16_kernel(const float* __restrict__ bias, float* __restrict__ out) {
    extern __shared__ __align__(1024) char smem[];
    const uint32_t sbase = smem_u32(smem);
    const int tid  = threadIdx.x;
    const int wid  = tid >> 5;
    const int lane = tid & 31;
    const int wm   = wid & 1;        // warp M coord (2)
    const int wn   = wid >> 1;       // warp N coord (2)

    // M-fastest CTA order: concurrent CTAs share B bands; A stays L2-resident.
    const int mt = blockIdx.x & (NMT - 1);  // 64 M tiles
    const int nt = blockIdx.x >> 6;         // 86 N tiles
    const int m0 = mt * BM;
    const int n0 = nt * BN;

    const __half* Abase = g_Xh + (size_t)m0 * IN_F;
    const __half* Bbase = g_Bh + (size_t)n0 * IN_F;

    // Stage loader: A 512 chunks of 16B (4/thread), B 1024 chunks (8/thread).
    auto load_stage = [&](int s, int kl) {
        const int k0 = kl * BK;
        const uint32_t abuf = sbase + s * STAGE_BYTES;
        const uint32_t bbuf = abuf + A_STAGE_BYTES;
        const __half* Ag = Abase + k0;
        const __half* Bg = Bbase + k0;
        #pragma unroll
        for (int j = 0; j < 4; j++) {
            int q = tid + j * NTHREADS;       // 0..511
            int r = q >> 3;                   // A row 0..63
            int c = q & 7;                    // 16B chunk 0..7
            uint32_t off = (uint32_t)(r * 128 + c * 16);
            uint32_t sw  = off ^ ((off >> 3) & 0x70);
            asm volatile("cp.async.cg.shared.global [%0], [%1], 16;"
                         :: "r"(abuf + sw), "l"(Ag + (size_t)r * IN_F + c * 8)
                         : "memory");
        }
        #pragma unroll
        for (int j = 0; j < 8; j++) {
            int q = tid + j * NTHREADS;       // 0..1023
            int r = q >> 3;                   // B row 0..127
            int c = q & 7;
            uint32_t off = (uint32_t)(r * 128 + c * 16);
            uint32_t sw  = off ^ ((off >> 3) & 0x70);
            asm volatile("cp.async.cg.shared.global [%0], [%1], 16;"
                         :: "r"(bbuf + sw), "l"(Bg + (size_t)r * IN_F + c * 8)
                         : "memory");
        }
    };

    // Prologue: fill stage 0
    load_stage(0, 0);
    asm volatile("cp.async.commit_group;" ::: "memory");

    float acc[2][8][4];
    #pragma unroll
    for (int mi = 0; mi < 2; mi++)
        #pragma unroll
        for (int nf = 0; nf < 8; nf++)
            #pragma unroll
            for (int e = 0; e < 4; e++) acc[mi][nf][e] = 0.0f;

    const int lrow   = lane & 15;    // ldmatrix source row within 16
    const int lchunk = lane >> 4;    // 0: k0-7 chunk, 1: k8-15 chunk

    for (int kt = 0; kt < NKIT; kt++) {
        asm volatile("cp.async.wait_group %0;" :: "n"(0) : "memory");
        __syncthreads();

        // Prefetch stage kt+1 (its buffer was consumed at kt-1; all warps
        // passed the barrier above, so it is free). Lands during compute(kt).
        const int kl = kt + 1;
        if (kl < NKIT) load_stage(kl & 1, kl);
        asm volatile("cp.async.commit_group;" ::: "memory");

        // Compute on stage s.
        const int s = kt & 1;
        const uint32_t abuf = sbase + s * STAGE_BYTES;
        const uint32_t bbuf = abuf + A_STAGE_BYTES;

        #pragma unroll
        for (int k16 = 0; k16 < BK / 16; k16++) {
            uint32_t af[2][4], bf[4][4];
            const int chunk = k16 * 2 + lchunk;
            #pragma unroll
            for (int mi = 0; mi < 2; mi++) {
                int row = wm * 32 + mi * 16 + lrow;
                uint32_t off = (uint32_t)(row * 128 + chunk * 16);
                ldsm_x4(abuf + (off ^ ((off >> 3) & 0x70)), af[mi]);
            }
            #pragma unroll
            for (int nj = 0; nj < 4; nj++) {
                int row = wn * 64 + nj * 16 + lrow;
                uint32_t off = (uint32_t)(row * 128 + chunk * 16);
                ldsm_x4(bbuf + (off ^ ((off >> 3) & 0x70)), bf[nj]);
            }
            #pragma unroll
            for (int mi = 0; mi < 2; mi++)
                #pragma unroll
                for (int nj = 0; nj < 4; nj++) {
                    mma16816(acc[mi][2 * nj],     af[mi], bf[nj][0], bf[nj][2]);
                    mma16816(acc[mi][2 * nj + 1], af[mi], bf[nj][1], bf[nj][3]);
                }
        }
    }

    // Epilogue: fragment layout c0,c1 -> (row=q, col=2c..2c+1), c2,c3 -> row+8.
    const int qrow = lane >> 2;          // 0..7
    const int qcol = (lane & 3) * 2;
    #pragma unroll
    for (int mi = 0; mi < 2; mi++) {
        int gr = m0 + wm * 32 + mi * 16 + qrow;
        float* p0 = out + (size_t)gr * OUT_F;
        float* p1 = p0 + 8 * OUT_F;
        #pragma unroll
        for (int nf = 0; nf < 8; nf++) {
            int col = n0 + wn * 64 + nf * 8 + qcol;
            float bx = __ldg(bias + col);
            float by = __ldg(bias + col + 1);
            float2 v0, v1;
            v0.x = acc[mi][nf][0] + bx;
            v0.y = acc[mi][nf][1] + by;
            v1.x = acc[mi][nf][2] + bx;
            v1.y = acc[mi][nf][3] + by;
            *reinterpret_cast<float2*>(p0 + col) = v0;
            *reinterpret_cast<float2*>(p1 + col) = v1;
        }
    }
}

// ---------------------------------------------------------------------------
extern "C" void kernel_launch(void* const* d_in, const int* in_sizes, int n_in,
                              void* d_out, int out_size) {
    const float*    x    = (const float*)   d_in[0];
    const uint32_t* qw   = (const uint32_t*)d_in[1];
    const uint32_t* qz   = (const uint32_t*)d_in[2];
    const float*    sc   = (const float*)   d_in[3];
    const float*    bias = (const float*)   d_in[4];
    float*          out  = (float*)d_out;

    // 1) fused: x -> fp16  ||  int4 dequant -> fp16 (concurrent)
    prep_kernel<<<NCONV_BLKS + NDEQ_BLKS, 256>>>((const float4*)x, qw, qz, sc);

    // 2) fp16 mma.sync GEMM, 4 CTAs/SM, 64x128 tiles, BK=64, 2 stages
    cudaFuncSetAttribute(gemm_f16_kernel,
                         cudaFuncAttributeMaxDynamicSharedMemorySize, SMEM_TOTAL);
    dim3 grid(NMT * NNT);  // 64 * 86 = 5504, M-fastest
    gemm_f16_kernel<<<grid, NTHREADS, SMEM_TOTAL>>>(bias, out);
}